// round 1
// baseline (speedup 1.0000x reference)
#include <cuda_runtime.h>

#define DIM   100
#define WW    40
#define NW    39          // words per slice (W-1)
#define NH    4
#define ALPHA 0.3f
#define NBLK  4800        // B*T*E = 8*30*20
#define NTHR  256

__global__ __launch_bounds__(NTHR, 1)
void tse_kernel(const float* __restrict__ x,
                const float* __restrict__ w_att,
                const float* __restrict__ b_att,
                float* __restrict__ out)
{
    __shared__ float sx[WW * DIM];     // row 0 = type_emb, rows 1..39 = words
    __shared__ float swa[NH * DIM];
    __shared__ float sba[NH * DIM];
    __shared__ float se[NH * NW];      // exp(scores)
    __shared__ float sinv[NH];         // 1 / sum_n exp(scores)

    const int tid = threadIdx.x;
    const long long bid = blockIdx.x;

    // ---- load the 40x100 slice (16 KB) with float4, plus attention params ----
    const float4* xs = reinterpret_cast<const float4*>(x + bid * (WW * DIM));
    float4* sx4 = reinterpret_cast<float4*>(sx);
    #pragma unroll
    for (int i = tid; i < (WW * DIM) / 4; i += NTHR) sx4[i] = xs[i];
    for (int i = tid; i < NH * DIM; i += NTHR) { swa[i] = w_att[i]; sba[i] = b_att[i]; }
    __syncthreads();

    // ---- phase 1: scores[h][n] = sum_d type[d] * leaky(words[n][d]*wa[h][d] + ba[h][d]) ----
    const int warp = tid >> 5;
    const int lane = tid & 31;
    for (int task = warp; task < NH * NW; task += (NTHR / 32)) {
        const int h = task / NW;
        const int n = task - h * NW;
        const float* wr = sx + (n + 1) * DIM;
        const float* wa = swa + h * DIM;
        const float* ba = sba + h * DIM;
        float acc = 0.f;
        #pragma unroll
        for (int d = lane; d < DIM; d += 32) {
            float pre = fmaf(wr[d], wa[d], ba[d]);
            float hid = (pre >= 0.f) ? pre : ALPHA * pre;
            acc = fmaf(sx[d], hid, acc);
        }
        #pragma unroll
        for (int off = 16; off; off >>= 1)
            acc += __shfl_down_sync(0xffffffffu, acc, off);
        if (lane == 0) se[task] = __expf(acc);
    }
    __syncthreads();

    // ---- phase 2: per-head normalizers ----
    if (tid < NH) {
        float s = 0.f;
        #pragma unroll
        for (int n = 0; n < NW; n++) s += se[tid * NW + n];
        sinv[tid] = 1.f / s;
    }
    __syncthreads();

    // ---- phase 3: out[h][d] = (1/sum) * sum_n e[h][n] * words[n][d] ----
    float* ob = out + bid * (NH * DIM);
    for (int task = tid; task < NH * DIM; task += NTHR) {
        const int h = task / DIM;
        const int d = task - h * DIM;
        const float* e = se + h * NW;
        float acc = 0.f;
        #pragma unroll
        for (int n = 0; n < NW; n++)
            acc = fmaf(e[n], sx[(n + 1) * DIM + d], acc);
        ob[task] = acc * sinv[h];
    }
}

extern "C" void kernel_launch(void* const* d_in, const int* in_sizes, int n_in,
                              void* d_out, int out_size)
{
    const float* x     = (const float*)d_in[0];
    const float* w_att = (const float*)d_in[1];
    const float* b_att = (const float*)d_in[2];
    float* out = (float*)d_out;
    tse_kernel<<<NBLK, NTHR>>>(x, w_att, b_att, out);
}

// round 2
// speedup vs baseline: 1.6663x; 1.6663x over previous
#include <cuda_runtime.h>

#define DIM   100
#define WW    40
#define NW    39
#define NH    4
#define ALPHA 0.3f
#define NBLK  4800        // B*T*E
#define NTHR  256
#define NWARP 8

__global__ __launch_bounds__(NTHR, 3)
void tse_kernel(const float* __restrict__ x,
                const float* __restrict__ w_att,
                const float* __restrict__ b_att,
                float* __restrict__ out)
{
    __shared__ float sx[WW * DIM];            // slice: row 0 = type, 1..39 = words
    __shared__ float se[NH * NW];             // exp(scores)
    __shared__ float sinv[NH];                // 1/sum
    __shared__ float sp[NWARP * NH * 4 * 32]; // per-warp partials (16 KB)

    const int tid  = threadIdx.x;
    const int warp = tid >> 5;
    const int lane = tid & 31;
    const long long bid = blockIdx.x;
    const float* __restrict__ xb = x + bid * (WW * DIM);

    // ---- stage slice into smem (float4) ----
    {
        const float4* xs  = reinterpret_cast<const float4*>(xb);
        float4*       sx4 = reinterpret_cast<float4*>(sx);
        #pragma unroll
        for (int i = tid; i < (WW * DIM) / 4; i += NTHR) sx4[i] = xs[i];
    }

    // ---- register-resident params at this lane's 4 d-slots ----
    const int  d0 = lane, d1 = lane + 32, d2 = lane + 64;
    const bool has3 = (lane < 4);
    const int  d3 = has3 ? (lane + 96) : 0;   // clamped; contribution zeroed via t3/w3

    float t0 = xb[d0], t1 = xb[d1], t2 = xb[d2];
    float t3 = has3 ? xb[d3] : 0.f;

    float wa[NH][4], ba[NH][4];
    #pragma unroll
    for (int h = 0; h < NH; h++) {
        const float* wah = w_att + h * DIM;
        const float* bah = b_att + h * DIM;
        wa[h][0] = wah[d0]; wa[h][1] = wah[d1]; wa[h][2] = wah[d2]; wa[h][3] = wah[d3];
        ba[h][0] = bah[d0]; ba[h][1] = bah[d1]; ba[h][2] = bah[d2]; ba[h][3] = bah[d3];
    }
    __syncthreads();

    // ---- phase 1: scores for all 4 heads per word-row read ----
    for (int n = warp; n < NW; n += NWARP) {
        const float* wr = sx + (n + 1) * DIM;
        const float w0 = wr[d0], w1 = wr[d1], w2 = wr[d2];
        const float w3 = has3 ? wr[d3] : 0.f;
        #pragma unroll
        for (int h = 0; h < NH; h++) {
            float p, acc;
            p = fmaf(w0, wa[h][0], ba[h][0]); p = (p >= 0.f) ? p : ALPHA * p; acc = t0 * p;
            p = fmaf(w1, wa[h][1], ba[h][1]); p = (p >= 0.f) ? p : ALPHA * p; acc = fmaf(t1, p, acc);
            p = fmaf(w2, wa[h][2], ba[h][2]); p = (p >= 0.f) ? p : ALPHA * p; acc = fmaf(t2, p, acc);
            p = fmaf(w3, wa[h][3], ba[h][3]); p = (p >= 0.f) ? p : ALPHA * p; acc = fmaf(t3, p, acc);
            #pragma unroll
            for (int off = 16; off; off >>= 1)
                acc += __shfl_down_sync(0xffffffffu, acc, off);
            if (lane == 0) se[h * NW + n] = __expf(acc);
        }
    }
    __syncthreads();

    // ---- phase 2: per-head normalizers (one warp per head) ----
    if (warp < NH) {
        float s = 0.f;
        for (int n = lane; n < NW; n += 32) s += se[warp * NW + n];
        #pragma unroll
        for (int off = 16; off; off >>= 1)
            s += __shfl_down_sync(0xffffffffu, s, off);
        if (lane == 0) sinv[warp] = 1.f / s;
    }
    __syncthreads();

    // ---- phase 3: register accumulators, one word-row read feeds 16 FMAs ----
    float acc[NH][4];
    #pragma unroll
    for (int h = 0; h < NH; h++)
        #pragma unroll
        for (int j = 0; j < 4; j++) acc[h][j] = 0.f;

    for (int n = warp; n < NW; n += NWARP) {
        const float* wr = sx + (n + 1) * DIM;
        const float w0 = wr[d0], w1 = wr[d1], w2 = wr[d2];
        const float w3 = has3 ? wr[d3] : 0.f;
        #pragma unroll
        for (int h = 0; h < NH; h++) {
            const float e = se[h * NW + n];
            acc[h][0] = fmaf(e, w0, acc[h][0]);
            acc[h][1] = fmaf(e, w1, acc[h][1]);
            acc[h][2] = fmaf(e, w2, acc[h][2]);
            acc[h][3] = fmaf(e, w3, acc[h][3]);
        }
    }

    // write per-warp partials
    #pragma unroll
    for (int h = 0; h < NH; h++)
        #pragma unroll
        for (int j = 0; j < 4; j++)
            sp[((warp * NH + h) * 4 + j) * 32 + lane] = acc[h][j];
    __syncthreads();

    // ---- final 8-way reduce + coalesced store ----
    float* ob = out + bid * (NH * DIM);
    #pragma unroll
    for (int s = tid; s < NH * 4 * 32; s += NTHR) {
        const int l = s & 31;
        const int j = (s >> 5) & 3;
        const int h = s >> 7;
        const int d = j * 32 + l;
        if (d < DIM) {
            float v = 0.f;
            #pragma unroll
            for (int w = 0; w < NWARP; w++)
                v += sp[((w * NH + h) * 4 + j) * 32 + l];
            ob[h * DIM + d] = v * sinv[h];
        }
    }
}

extern "C" void kernel_launch(void* const* d_in, const int* in_sizes, int n_in,
                              void* d_out, int out_size)
{
    const float* x     = (const float*)d_in[0];
    const float* w_att = (const float*)d_in[1];
    const float* b_att = (const float*)d_in[2];
    float* out = (float*)d_out;
    tse_kernel<<<NBLK, NTHR>>>(x, w_att, b_att, out);
}

// round 3
// speedup vs baseline: 2.0418x; 1.2254x over previous
#include <cuda_runtime.h>

#define DIM   100
#define NW    39
#define NH    4
#define NBLK  4800
#define NTHR  256
#define NWARP 8
#define NQ    25          // float4 chunks per 100-float row

__global__ __launch_bounds__(NTHR)
void tse_kernel(const float* __restrict__ x,
                const float* __restrict__ w_att,
                const float* __restrict__ b_att,
                float* __restrict__ out)
{
    __shared__ __align__(16) float sbuf[40 * DIM];   // slice; reused for partials
    __shared__ __align__(16) float se[NW * NH];      // exp(scores), [n][h]
    __shared__ float sinv[NH];

    const int tid  = threadIdx.x;
    const int warp = tid >> 5;
    const int lane = tid & 31;
    const long long bid = blockIdx.x;
    const float* __restrict__ xb = x + bid * (40 * DIM);

    // ---- stage slice (16 KB) ----
    {
        const float4* xs  = reinterpret_cast<const float4*>(xb);
        float4*       sx4 = reinterpret_cast<float4*>(sbuf);
        #pragma unroll
        for (int i = tid; i < 1000; i += NTHR) sx4[i] = xs[i];
    }

    // ---- register params: lane owns d = 4*lane .. 4*lane+3 (lanes 0..24) ----
    const bool act = (lane < NQ);
    float4 t4 = make_float4(0.f, 0.f, 0.f, 0.f);
    float4 wa4[NH], ba4[NH];
    #pragma unroll
    for (int h = 0; h < NH; h++) {
        wa4[h] = make_float4(0.f, 0.f, 0.f, 0.f);
        ba4[h] = make_float4(0.f, 0.f, 0.f, 0.f);
    }
    if (act) {
        t4 = reinterpret_cast<const float4*>(xb)[lane];
        #pragma unroll
        for (int h = 0; h < NH; h++) {
            wa4[h] = reinterpret_cast<const float4*>(w_att + h * DIM)[lane];
            ba4[h] = reinterpret_cast<const float4*>(b_att + h * DIM)[lane];
        }
    }
    __syncthreads();

    // ---- phase 1: 4 head scores per word row, 6-shuffle packed reduction ----
    for (int n = warp; n < NW; n += NWARP) {
        float4 w4 = make_float4(0.f, 0.f, 0.f, 0.f);
        if (act) w4 = reinterpret_cast<const float4*>(sbuf + (n + 1) * DIM)[lane];

        float a[NH];
        #pragma unroll
        for (int h = 0; h < NH; h++) {
            float p, s;
            p = fmaf(w4.x, wa4[h].x, ba4[h].x); p = fmaxf(p, 0.3f * p); s = t4.x * p;
            p = fmaf(w4.y, wa4[h].y, ba4[h].y); p = fmaxf(p, 0.3f * p); s = fmaf(t4.y, p, s);
            p = fmaf(w4.z, wa4[h].z, ba4[h].z); p = fmaxf(p, 0.3f * p); s = fmaf(t4.z, p, s);
            p = fmaf(w4.w, wa4[h].w, ba4[h].w); p = fmaxf(p, 0.3f * p); s = fmaf(t4.w, p, s);
            a[h] = s;
        }

        // packed reduction: after it, lanes 0-7 hold h0 sum, 8-15 h1, 16-23 h2, 24-31 h3
        const bool lo = (lane < 16);
        float xv = __shfl_xor_sync(0xffffffffu, lo ? a[2] : a[0], 16);
        float yv = __shfl_xor_sync(0xffffffffu, lo ? a[3] : a[1], 16);
        float u0 = (lo ? a[0] : a[2]) + xv;
        float u1 = (lo ? a[1] : a[3]) + yv;
        const bool b3 = (lane & 8) != 0;
        float zv = __shfl_xor_sync(0xffffffffu, b3 ? u0 : u1, 8);
        float t  = (b3 ? u1 : u0) + zv;
        t += __shfl_xor_sync(0xffffffffu, t, 4);
        t += __shfl_xor_sync(0xffffffffu, t, 2);
        t += __shfl_xor_sync(0xffffffffu, t, 1);
        if ((lane & 7) == 0) se[n * NH + (lane >> 3)] = __expf(t);
    }
    __syncthreads();

    // ---- phase 2: normalizers, one warp per head ----
    if (warp < NH) {
        float s = (lane < NW) ? se[lane * NH + warp] : 0.f;
        if (lane + 32 < NW) s += se[(lane + 32) * NH + warp];
        #pragma unroll
        for (int off = 16; off; off >>= 1)
            s += __shfl_xor_sync(0xffffffffu, s, off);
        if (lane == 0) sinv[warp] = 1.f / s;
    }
    __syncthreads();

    // ---- phase 3: one word-row LDS.128 + one se LDS.128 feed 16 FMAs ----
    float4 acc[NH];
    #pragma unroll
    for (int h = 0; h < NH; h++) acc[h] = make_float4(0.f, 0.f, 0.f, 0.f);

    for (int n = warp; n < NW; n += NWARP) {
        float4 w4 = make_float4(0.f, 0.f, 0.f, 0.f);
        if (act) w4 = reinterpret_cast<const float4*>(sbuf + (n + 1) * DIM)[lane];
        const float4 e4 = *reinterpret_cast<const float4*>(se + n * NH);
        acc[0].x = fmaf(e4.x, w4.x, acc[0].x); acc[0].y = fmaf(e4.x, w4.y, acc[0].y);
        acc[0].z = fmaf(e4.x, w4.z, acc[0].z); acc[0].w = fmaf(e4.x, w4.w, acc[0].w);
        acc[1].x = fmaf(e4.y, w4.x, acc[1].x); acc[1].y = fmaf(e4.y, w4.y, acc[1].y);
        acc[1].z = fmaf(e4.y, w4.z, acc[1].z); acc[1].w = fmaf(e4.y, w4.w, acc[1].w);
        acc[2].x = fmaf(e4.z, w4.x, acc[2].x); acc[2].y = fmaf(e4.z, w4.y, acc[2].y);
        acc[2].z = fmaf(e4.z, w4.z, acc[2].z); acc[2].w = fmaf(e4.z, w4.w, acc[2].w);
        acc[3].x = fmaf(e4.w, w4.x, acc[3].x); acc[3].y = fmaf(e4.w, w4.y, acc[3].y);
        acc[3].z = fmaf(e4.w, w4.z, acc[3].z); acc[3].w = fmaf(e4.w, w4.w, acc[3].w);
    }
    __syncthreads();    // slice reads done; safe to overwrite sbuf with partials

    // ---- partials (float4) into the reused slice buffer ----
    {
        float4* sp4 = reinterpret_cast<float4*>(sbuf);
        if (act) {
            #pragma unroll
            for (int h = 0; h < NH; h++)
                sp4[(warp * NH + h) * NQ + lane] = acc[h];
        }
    }
    __syncthreads();

    // ---- cross-warp reduce + coalesced float4 store ----
    if (tid < NH * NQ) {
        const int h = tid / NQ;
        const float4* sp4 = reinterpret_cast<const float4*>(sbuf);
        float4 v = sp4[h * NQ + (tid - h * NQ)];
        #pragma unroll
        for (int w = 1; w < NWARP; w++) {
            const float4 p = sp4[(w * NH + h) * NQ + (tid - h * NQ)];
            v.x += p.x; v.y += p.y; v.z += p.z; v.w += p.w;
        }
        const float si = sinv[h];
        v.x *= si; v.y *= si; v.z *= si; v.w *= si;
        reinterpret_cast<float4*>(out + bid * (NH * DIM))[tid] = v;
    }
}

extern "C" void kernel_launch(void* const* d_in, const int* in_sizes, int n_in,
                              void* d_out, int out_size)
{
    const float* x     = (const float*)d_in[0];
    const float* w_att = (const float*)d_in[1];
    const float* b_att = (const float*)d_in[2];
    float* out = (float*)d_out;
    tse_kernel<<<NBLK, NTHR>>>(x, w_att, b_att, out);
}

// round 5
// speedup vs baseline: 2.2525x; 1.1032x over previous
#include <cuda_runtime.h>

#define DIM   100
#define NW    39
#define NH    4
#define NBLK  4800
#define NTHR  256
#define NWARP 8
#define NQ    25          // float4 chunks per 100-float row
#define RPW   5           // rows per warp (ceil(39/8))

__global__ __launch_bounds__(NTHR, 3)
void tse_kernel(const float* __restrict__ x,
                const float* __restrict__ w_att,
                const float* __restrict__ b_att,
                float* __restrict__ out)
{
    __shared__ __align__(16) float se[40 * NH];                 // exp(scores) [n][h]
    __shared__ float sinv[NH];
    __shared__ __align__(16) float4 sp4[NWARP * NH * NQ];       // partials (12.8 KB)

    const int tid  = threadIdx.x;
    const int warp = tid >> 5;
    const int lane = tid & 31;
    const long long bid = blockIdx.x;
    const float* __restrict__ xb = x + bid * (40 * DIM);
    const bool act = (lane < NQ);

    // ---- register-resident params ----
    float4 t4 = make_float4(0.f, 0.f, 0.f, 0.f);
    float4 wa4[NH], ba4[NH];
    #pragma unroll
    for (int h = 0; h < NH; h++) {
        wa4[h] = make_float4(0.f, 0.f, 0.f, 0.f);
        ba4[h] = make_float4(0.f, 0.f, 0.f, 0.f);
    }
    if (act) {
        t4 = reinterpret_cast<const float4*>(xb)[lane];
        #pragma unroll
        for (int h = 0; h < NH; h++) {
            wa4[h] = reinterpret_cast<const float4*>(w_att + h * DIM)[lane];
            ba4[h] = reinterpret_cast<const float4*>(b_att + h * DIM)[lane];
        }
    }

    // ---- register-resident word rows: warp owns n = warp + 8k ----
    float4 w4[RPW];
    #pragma unroll
    for (int k = 0; k < RPW; k++) {
        const int n = warp + k * NWARP;
        w4[k] = make_float4(0.f, 0.f, 0.f, 0.f);
        if (act && n < NW)
            w4[k] = *reinterpret_cast<const float4*>(xb + (n + 1) * DIM + 4 * lane);
    }

    // ---- phase 1: 4 head scores per owned row, 6-shuffle packed reduction ----
    #pragma unroll
    for (int k = 0; k < RPW; k++) {
        const int n = warp + k * NWARP;
        float a[NH];
        #pragma unroll
        for (int h = 0; h < NH; h++) {
            float p, s;
            p = fmaf(w4[k].x, wa4[h].x, ba4[h].x); p = fmaxf(p, 0.3f * p); s = t4.x * p;
            p = fmaf(w4[k].y, wa4[h].y, ba4[h].y); p = fmaxf(p, 0.3f * p); s = fmaf(t4.y, p, s);
            p = fmaf(w4[k].z, wa4[h].z, ba4[h].z); p = fmaxf(p, 0.3f * p); s = fmaf(t4.z, p, s);
            p = fmaf(w4[k].w, wa4[h].w, ba4[h].w); p = fmaxf(p, 0.3f * p); s = fmaf(t4.w, p, s);
            a[h] = s;
        }
        // packed reduction: lanes 0-7 -> h0, 8-15 -> h1, 16-23 -> h2, 24-31 -> h3
        const bool lo = (lane < 16);
        float xv = __shfl_xor_sync(0xffffffffu, lo ? a[2] : a[0], 16);
        float yv = __shfl_xor_sync(0xffffffffu, lo ? a[3] : a[1], 16);
        float u0 = (lo ? a[0] : a[2]) + xv;
        float u1 = (lo ? a[1] : a[3]) + yv;
        const bool b3 = (lane & 8) != 0;
        float zv = __shfl_xor_sync(0xffffffffu, b3 ? u0 : u1, 8);
        float t  = (b3 ? u1 : u0) + zv;
        t += __shfl_xor_sync(0xffffffffu, t, 4);
        t += __shfl_xor_sync(0xffffffffu, t, 2);
        t += __shfl_xor_sync(0xffffffffu, t, 1);
        if (((lane & 7) == 0) && n < NW) se[n * NH + (lane >> 3)] = __expf(t);
    }
    __syncthreads();

    // ---- phase 2: normalizers, one warp per head ----
    if (warp < NH) {
        float s = (lane < NW) ? se[lane * NH + warp] : 0.f;
        if (lane + 32 < NW) s += se[(lane + 32) * NH + warp];
        #pragma unroll
        for (int off = 16; off; off >>= 1)
            s += __shfl_xor_sync(0xffffffffu, s, off);
        if (lane == 0) sinv[warp] = 1.f / s;
    }
    __syncthreads();

    // ---- phase 3: accumulate from register-resident rows ----
    float4 acc[NH];
    #pragma unroll
    for (int h = 0; h < NH; h++) acc[h] = make_float4(0.f, 0.f, 0.f, 0.f);

    #pragma unroll
    for (int k = 0; k < RPW; k++) {
        const int n = warp + k * NWARP;
        float4 e4 = make_float4(0.f, 0.f, 0.f, 0.f);
        if (n < NW) e4 = *reinterpret_cast<const float4*>(se + n * NH);  // broadcast
        acc[0].x = fmaf(e4.x, w4[k].x, acc[0].x); acc[0].y = fmaf(e4.x, w4[k].y, acc[0].y);
        acc[0].z = fmaf(e4.x, w4[k].z, acc[0].z); acc[0].w = fmaf(e4.x, w4[k].w, acc[0].w);
        acc[1].x = fmaf(e4.y, w4[k].x, acc[1].x); acc[1].y = fmaf(e4.y, w4[k].y, acc[1].y);
        acc[1].z = fmaf(e4.y, w4[k].z, acc[1].z); acc[1].w = fmaf(e4.y, w4[k].w, acc[1].w);
        acc[2].x = fmaf(e4.z, w4[k].x, acc[2].x); acc[2].y = fmaf(e4.z, w4[k].y, acc[2].y);
        acc[2].z = fmaf(e4.z, w4[k].z, acc[2].z); acc[2].w = fmaf(e4.z, w4[k].w, acc[2].w);
        acc[3].x = fmaf(e4.w, w4[k].x, acc[3].x); acc[3].y = fmaf(e4.w, w4[k].y, acc[3].y);
        acc[3].z = fmaf(e4.w, w4[k].z, acc[3].z); acc[3].w = fmaf(e4.w, w4[k].w, acc[3].w);
    }

    // ---- per-warp partials ----
    if (act) {
        #pragma unroll
        for (int h = 0; h < NH; h++)
            sp4[(warp * NH + h) * NQ + lane] = acc[h];
    }
    __syncthreads();

    // ---- cross-warp reduce + coalesced float4 store ----
    if (tid < NH * NQ) {
        const int h = tid / NQ;
        const int i = tid - h * NQ;
        float4 v = sp4[h * NQ + i];
        #pragma unroll
        for (int w = 1; w < NWARP; w++) {
            const float4 p = sp4[(w * NH + h) * NQ + i];
            v.x += p.x; v.y += p.y; v.z += p.z; v.w += p.w;
        }
        const float si = sinv[h];
        v.x *= si; v.y *= si; v.z *= si; v.w *= si;
        reinterpret_cast<float4*>(out + bid * (NH * DIM))[tid] = v;
    }
}

extern "C" void kernel_launch(void* const* d_in, const int* in_sizes, int n_in,
                              void* d_out, int out_size)
{
    const float* x     = (const float*)d_in[0];
    const float* w_att = (const float*)d_in[1];
    const float* b_att = (const float*)d_in[2];
    float* out = (float*)d_out;
    tse_kernel<<<NBLK, NTHR>>>(x, w_att, b_att, out);
}

// round 6
// speedup vs baseline: 2.3480x; 1.0424x over previous
#include <cuda_runtime.h>

#define DIM   100
#define NW    39
#define NH    4
#define NBLK  4800
#define NTHR  256
#define NWARP 8
#define NQ    25          // float4 chunks per 100-float row
#define RPW   5           // rows per warp (ceil(39/8))

__global__ __launch_bounds__(NTHR, 4)
void tse_kernel(const float* __restrict__ x,
                const float* __restrict__ w_att,
                const float* __restrict__ b_att,
                float* __restrict__ out)
{
    __shared__ __align__(16) float se[40 * NH];                 // exp(scores) [n][h]
    __shared__ float sinv[NH];
    __shared__ __align__(16) float4 sp4[NWARP * NH * NQ];       // partials (12.8 KB)

    const int tid  = threadIdx.x;
    const int warp = tid >> 5;
    const int lane = tid & 31;
    const int bid  = blockIdx.x;                 // 32-bit: 4800*4000 fits int
    const float* __restrict__ xb = x + bid * (40 * DIM);
    const bool act = (lane < NQ);

    // ---- register-resident params ----
    float4 t4 = make_float4(0.f, 0.f, 0.f, 0.f);
    float4 wa4[NH], ba4[NH];
    #pragma unroll
    for (int h = 0; h < NH; h++) {
        wa4[h] = make_float4(0.f, 0.f, 0.f, 0.f);
        ba4[h] = make_float4(0.f, 0.f, 0.f, 0.f);
    }
    if (act) {
        t4 = reinterpret_cast<const float4*>(xb)[lane];
        #pragma unroll
        for (int h = 0; h < NH; h++) {
            wa4[h] = reinterpret_cast<const float4*>(w_att + h * DIM)[lane];
            ba4[h] = reinterpret_cast<const float4*>(b_att + h * DIM)[lane];
        }
    }

    // row pointer for this lane (row n lives at xb + (n+1)*DIM + 4*lane)
    const float* __restrict__ rp = xb + DIM + 4 * lane;

    // ---- phase 1: double-buffered row loads, 6-shuffle packed reduction ----
    float4 w_cur = make_float4(0.f, 0.f, 0.f, 0.f);
    if (act) w_cur = *reinterpret_cast<const float4*>(rp + warp * DIM);

    #pragma unroll
    for (int k = 0; k < RPW; k++) {
        const int n = warp + k * NWARP;
        // prefetch next row before reducing current one
        float4 w_nxt = make_float4(0.f, 0.f, 0.f, 0.f);
        if (k + 1 < RPW) {
            const int n2 = warp + (k + 1) * NWARP;
            if (act && n2 < NW)
                w_nxt = *reinterpret_cast<const float4*>(rp + n2 * DIM);
        }

        float a[NH];
        #pragma unroll
        for (int h = 0; h < NH; h++) {
            float p, s;
            p = fmaf(w_cur.x, wa4[h].x, ba4[h].x); p = fmaxf(p, 0.3f * p); s = t4.x * p;
            p = fmaf(w_cur.y, wa4[h].y, ba4[h].y); p = fmaxf(p, 0.3f * p); s = fmaf(t4.y, p, s);
            p = fmaf(w_cur.z, wa4[h].z, ba4[h].z); p = fmaxf(p, 0.3f * p); s = fmaf(t4.z, p, s);
            p = fmaf(w_cur.w, wa4[h].w, ba4[h].w); p = fmaxf(p, 0.3f * p); s = fmaf(t4.w, p, s);
            a[h] = s;
        }
        // packed reduction: lanes 0-7 -> h0, 8-15 -> h1, 16-23 -> h2, 24-31 -> h3
        const bool lo = (lane < 16);
        float xv = __shfl_xor_sync(0xffffffffu, lo ? a[2] : a[0], 16);
        float yv = __shfl_xor_sync(0xffffffffu, lo ? a[3] : a[1], 16);
        float u0 = (lo ? a[0] : a[2]) + xv;
        float u1 = (lo ? a[1] : a[3]) + yv;
        const bool b3 = (lane & 8) != 0;
        float zv = __shfl_xor_sync(0xffffffffu, b3 ? u0 : u1, 8);
        float t  = (b3 ? u1 : u0) + zv;
        t += __shfl_xor_sync(0xffffffffu, t, 4);
        t += __shfl_xor_sync(0xffffffffu, t, 2);
        t += __shfl_xor_sync(0xffffffffu, t, 1);
        if (((lane & 7) == 0) && n < NW) se[n * NH + (lane >> 3)] = __expf(t);

        w_cur = w_nxt;
    }
    __syncthreads();

    // ---- phase 2: normalizers, one warp per head ----
    if (warp < NH) {
        float s = (lane < NW) ? se[lane * NH + warp] : 0.f;
        if (lane + 32 < NW) s += se[(lane + 32) * NH + warp];
        #pragma unroll
        for (int off = 16; off; off >>= 1)
            s += __shfl_xor_sync(0xffffffffu, s, off);
        if (lane == 0) sinv[warp] = 1.f / s;
    }
    __syncthreads();

    // ---- phase 3: rows re-loaded (L1-hot) with double-buffer ----
    float4 acc[NH];
    #pragma unroll
    for (int h = 0; h < NH; h++) acc[h] = make_float4(0.f, 0.f, 0.f, 0.f);

    if (act) w_cur = *reinterpret_cast<const float4*>(rp + warp * DIM);
    else     w_cur = make_float4(0.f, 0.f, 0.f, 0.f);

    #pragma unroll
    for (int k = 0; k < RPW; k++) {
        const int n = warp + k * NWARP;
        float4 w_nxt = make_float4(0.f, 0.f, 0.f, 0.f);
        if (k + 1 < RPW) {
            const int n2 = warp + (k + 1) * NWARP;
            if (act && n2 < NW)
                w_nxt = *reinterpret_cast<const float4*>(rp + n2 * DIM);
        }

        float4 e4 = make_float4(0.f, 0.f, 0.f, 0.f);
        if (n < NW) e4 = *reinterpret_cast<const float4*>(se + n * NH);  // broadcast
        acc[0].x = fmaf(e4.x, w_cur.x, acc[0].x); acc[0].y = fmaf(e4.x, w_cur.y, acc[0].y);
        acc[0].z = fmaf(e4.x, w_cur.z, acc[0].z); acc[0].w = fmaf(e4.x, w_cur.w, acc[0].w);
        acc[1].x = fmaf(e4.y, w_cur.x, acc[1].x); acc[1].y = fmaf(e4.y, w_cur.y, acc[1].y);
        acc[1].z = fmaf(e4.y, w_cur.z, acc[1].z); acc[1].w = fmaf(e4.y, w_cur.w, acc[1].w);
        acc[2].x = fmaf(e4.z, w_cur.x, acc[2].x); acc[2].y = fmaf(e4.z, w_cur.y, acc[2].y);
        acc[2].z = fmaf(e4.z, w_cur.z, acc[2].z); acc[2].w = fmaf(e4.z, w_cur.w, acc[2].w);
        acc[3].x = fmaf(e4.w, w_cur.x, acc[3].x); acc[3].y = fmaf(e4.w, w_cur.y, acc[3].y);
        acc[3].z = fmaf(e4.w, w_cur.z, acc[3].z); acc[3].w = fmaf(e4.w, w_cur.w, acc[3].w);

        w_cur = w_nxt;
    }

    // ---- per-warp partials ----
    if (act) {
        #pragma unroll
        for (int h = 0; h < NH; h++)
            sp4[(warp * NH + h) * NQ + lane] = acc[h];
    }
    __syncthreads();

    // ---- cross-warp reduce + coalesced float4 store ----
    if (tid < NH * NQ) {
        const int h = tid / NQ;
        const int i = tid - h * NQ;
        float4 v = sp4[h * NQ + i];
        #pragma unroll
        for (int w = 1; w < NWARP; w++) {
            const float4 p = sp4[(w * NH + h) * NQ + i];
            v.x += p.x; v.y += p.y; v.z += p.z; v.w += p.w;
        }
        const float si = sinv[h];
        v.x *= si; v.y *= si; v.z *= si; v.w *= si;
        reinterpret_cast<float4*>(out + bid * (NH * DIM))[tid] = v;
    }
}

extern "C" void kernel_launch(void* const* d_in, const int* in_sizes, int n_in,
                              void* d_out, int out_size)
{
    const float* x     = (const float*)d_in[0];
    const float* w_att = (const float*)d_in[1];
    const float* b_att = (const float*)d_in[2];
    float* out = (float*)d_out;
    tse_kernel<<<NBLK, NTHR>>>(x, w_att, b_att, out);
}